// round 3
// baseline (speedup 1.0000x reference)
#include <cuda_runtime.h>
#include <cuda_bf16.h>
#include <cstdint>
#include <cstddef>

#define DEV_INLINE __device__ __forceinline__

// B=8, C=64, S=256, WS=32, P=4, HEADS=8, DH=64
constexpr int NTOK = 32768;      // 512 windows * 64 tokens
constexpr int TOKD = 1024;
constexpr int QKVD = 1536;
constexpr int INNERD = 512;

// ---- static scratch ----
__device__ float g_tokens[(size_t)NTOK * TOKD];
__device__ float g_qkv[(size_t)NTOK * QKVD];
__device__ float g_o[(size_t)NTOK * INNERD];
__device__ float g_outp[(size_t)NTOK * TOKD];
__device__ float g_wqkv[(size_t)TOKD * QKVD];
__device__ float g_wout[(size_t)INNERD * TOKD];
__device__ float g_bias[TOKD];

DEV_INLINE float tf32r(float v) {
    uint32_t u; asm("cvt.rna.tf32.f32 %0, %1;" : "=r"(u) : "f"(v));
    return __uint_as_float(u);
}
DEV_INLINE void mma8(float* d, const uint32_t* a, const uint32_t* b) {
    asm volatile("mma.sync.aligned.m16n8k8.row.col.f32.tf32.tf32.f32 "
        "{%0,%1,%2,%3}, {%4,%5,%6,%7}, {%8,%9}, {%0,%1,%2,%3};"
        : "+f"(d[0]), "+f"(d[1]), "+f"(d[2]), "+f"(d[3])
        : "r"(a[0]), "r"(a[1]), "r"(a[2]), "r"(a[3]), "r"(b[0]), "r"(b[1]));
}
DEV_INLINE void cp16(float* dst, const float* src) {
    uint32_t a = (uint32_t)__cvta_generic_to_shared(dst);
    asm volatile("cp.async.ca.shared.global [%0], [%1], 16;" :: "r"(a), "l"(src));
}

// ---- weight permutation: d' = c*16 + p1*4 + p2 ; orig d = (p1*4+p2)*64 + c ----
__global__ void perm_wqkv_k(const float* __restrict__ w) {
    int dp = blockIdx.x;                       // d' 0..1023
    int src = (dp & 15) * 64 + (dp >> 4);
    float4 v = ((const float4*)(w + (size_t)src * QKVD))[threadIdx.x];  // 384 thr
    v.x = tf32r(v.x); v.y = tf32r(v.y); v.z = tf32r(v.z); v.w = tf32r(v.w);
    ((float4*)(g_wqkv + (size_t)dp * QKVD))[threadIdx.x] = v;
}
__global__ void perm_wout_k(const float* __restrict__ w, const float* __restrict__ b) {
    int e = blockIdx.x;                        // 0..511
    int dp = threadIdx.x;                      // 0..1023
    int src = (dp & 15) * 64 + (dp >> 4);
    g_wout[(size_t)e * TOKD + dp] = tf32r(w[(size_t)e * TOKD + src]);
    if (e == 0) g_bias[dp] = b[src];
}

// ---- gather: x[b,c,h,w] -> tokens[win*64+t][d'] (tf32-rounded) ----
__global__ void gather_k(const float* __restrict__ x) {
    int blk = blockIdx.x;                // 2048 = b*256 + h
    int b = blk >> 8, h = blk & 255;
    int tid = threadIdx.x;               // 256
    int w4 = tid & 63, c0 = tid >> 6;    // w4 = float4 idx over w
    int h1 = h >> 5, hh = h & 31, nh_i = hh >> 2, p1 = hh & 3;
    int w1 = w4 >> 3, nw_j = w4 & 7;
    int win = b * 64 + h1 * 8 + w1;
    int t = nh_i * 8 + nw_j;
    size_t drow = ((size_t)win * 64 + t) * TOKD + p1 * 4;
    size_t sbase = (((size_t)b * 64) * 256 + h) * 256 + w4 * 4;
#pragma unroll
    for (int i = 0; i < 16; i++) {
        int c = c0 * 16 + i;
        float4 v = *(const float4*)&x[sbase + (size_t)c * 65536];
        v.x = tf32r(v.x); v.y = tf32r(v.y); v.z = tf32r(v.z); v.w = tf32r(v.w);
        *(float4*)&g_tokens[drow + (size_t)c * 16] = v;
    }
}

// ---- scatter: g_outp[tok][d'] -> out[b,c,h,w] ----
__global__ void scatter_k(float* __restrict__ out) {
    int blk = blockIdx.x;
    int b = blk >> 8, h = blk & 255;
    int tid = threadIdx.x;
    int w4 = tid & 63, c0 = tid >> 6;
    int h1 = h >> 5, hh = h & 31, nh_i = hh >> 2, p1 = hh & 3;
    int w1 = w4 >> 3, nw_j = w4 & 7;
    int win = b * 64 + h1 * 8 + w1;
    int t = nh_i * 8 + nw_j;
    size_t srow = ((size_t)win * 64 + t) * TOKD + p1 * 4;
    size_t dbase = (((size_t)b * 64) * 256 + h) * 256 + w4 * 4;
#pragma unroll
    for (int i = 0; i < 16; i++) {
        int c = c0 * 16 + i;
        float4 v = *(const float4*)&g_outp[srow + (size_t)c * 16];
        *(float4*)&out[dbase + (size_t)c * 65536] = v;
    }
}

// ---- tf32 GEMM: 128x128 tile, K-step 16, 256 threads, 8 warps (2x4) ----
// MODE 0: g_qkv = g_tokens @ g_wqkv        (K=1024, N=1536)
// MODE 1: g_outp = g_o @ g_wout + bias     (K=512,  N=1024)
template<int K, int N, int MODE>
__global__ void __launch_bounds__(256) gemm_tf32_k() {
    __shared__ float As[128 * 20];   // [128 rows][16 k], stride 20
    __shared__ float Bs[16 * 136];   // [16 k][128 n],  stride 136
    const float* A = (MODE == 0) ? g_tokens : g_o;
    const float* B = (MODE == 0) ? g_wqkv : g_wout;
    float* C       = (MODE == 0) ? g_qkv : g_outp;

    const int tid = threadIdx.x, warp = tid >> 5, lane = tid & 31;
    const int wm = warp >> 2, wn = warp & 3;       // 2 x 4 warps
    const int tm = blockIdx.y * 128, tn = blockIdx.x * 128;
    const int r0 = lane >> 2, kk = lane & 3;

    float acc[4][4][4];
#pragma unroll
    for (int mi = 0; mi < 4; mi++)
#pragma unroll
        for (int ni = 0; ni < 4; ni++)
#pragma unroll
            for (int j = 0; j < 4; j++) acc[mi][ni][j] = 0.f;

    for (int k0 = 0; k0 < K; k0 += 16) {
        __syncthreads();
#pragma unroll
        for (int i = 0; i < 2; i++) {
            int idx = tid + i * 256;
            int r = idx >> 2, k4 = idx & 3;
            cp16(&As[r * 20 + k4 * 4], &A[(size_t)(tm + r) * K + k0 + k4 * 4]);
        }
#pragma unroll
        for (int i = 0; i < 2; i++) {
            int idx = tid + i * 256;
            int r = idx >> 5, n4 = idx & 31;
            cp16(&Bs[r * 136 + n4 * 4], &B[(size_t)(k0 + r) * N + tn + n4 * 4]);
        }
        asm volatile("cp.async.commit_group;");
        asm volatile("cp.async.wait_group 0;");
        __syncthreads();
#pragma unroll
        for (int k8 = 0; k8 < 2; k8++) {
            const int kb = k8 * 8;
            uint32_t a[4][4], bq[4][2];
#pragma unroll
            for (int mi = 0; mi < 4; mi++) {
                int rb = (wm * 64 + mi * 16) * 20 + kb + kk;
                a[mi][0] = __float_as_uint(As[rb + r0 * 20]);
                a[mi][1] = __float_as_uint(As[rb + (r0 + 8) * 20]);
                a[mi][2] = __float_as_uint(As[rb + r0 * 20 + 4]);
                a[mi][3] = __float_as_uint(As[rb + (r0 + 8) * 20 + 4]);
            }
#pragma unroll
            for (int ni = 0; ni < 4; ni++) {
                int cb = wn * 32 + ni * 8 + r0;
                bq[ni][0] = __float_as_uint(Bs[(kb + kk) * 136 + cb]);
                bq[ni][1] = __float_as_uint(Bs[(kb + kk + 4) * 136 + cb]);
            }
#pragma unroll
            for (int mi = 0; mi < 4; mi++)
#pragma unroll
                for (int ni = 0; ni < 4; ni++)
                    mma8(acc[mi][ni], a[mi], bq[ni]);
        }
    }
    // epilogue
    const int c2 = (lane & 3) * 2;
#pragma unroll
    for (int mi = 0; mi < 4; mi++) {
#pragma unroll
        for (int ni = 0; ni < 4; ni++) {
            int row = tm + wm * 64 + mi * 16 + r0;
            int col = tn + wn * 32 + ni * 8 + c2;
            float b0 = 0.f, b1 = 0.f;
            if (MODE == 1) { b0 = g_bias[col]; b1 = g_bias[col + 1]; }
            *(float2*)&C[(size_t)row * N + col] =
                make_float2(acc[mi][ni][0] + b0, acc[mi][ni][1] + b1);
            *(float2*)&C[(size_t)(row + 8) * N + col] =
                make_float2(acc[mi][ni][2] + b0, acc[mi][ni][3] + b1);
        }
    }
}

// ---- attention: one CTA per (window, head), 64 threads ----
__global__ void __launch_bounds__(64) attn_k() {
    __shared__ float Ks[64 * 64];
    __shared__ float Vs[64 * 64];
    __shared__ float St[64 * 64];   // transposed scores [k][t]
    const int win = blockIdx.y, hd = blockIdx.x, t = threadIdx.x;
    const float* base = g_qkv + (size_t)win * 64 * QKVD;
    // cooperative K/V load (coalesced float4)
#pragma unroll
    for (int i = 0; i < 16; i++) {
        int idx = i * 64 + t;
        int r = idx >> 4, v = idx & 15;
        *(float4*)&Ks[r * 64 + v * 4] =
            *(const float4*)&base[(size_t)r * QKVD + INNERD + hd * 64 + v * 4];
        *(float4*)&Vs[r * 64 + v * 4] =
            *(const float4*)&base[(size_t)r * QKVD + 2 * INNERD + hd * 64 + v * 4];
    }
    float q[64];
    const float* qrow = base + (size_t)t * QKVD + hd * 64;
#pragma unroll
    for (int d = 0; d < 64; d++) q[d] = qrow[d] * 0.125f;
    __syncthreads();
    // scores: S[k][t]
    for (int k = 0; k < 64; k++) {
        float s = 0.f;
#pragma unroll
        for (int d = 0; d < 64; d++) s += q[d] * Ks[k * 64 + d];
        St[k * 64 + t] = s;
    }
    // softmax over k (thread-private column, no sync needed)
    float m = -1e30f;
#pragma unroll 8
    for (int k = 0; k < 64; k++) m = fmaxf(m, St[k * 64 + t]);
    float sum = 0.f;
#pragma unroll 8
    for (int k = 0; k < 64; k++) {
        float p = __expf(St[k * 64 + t] - m);
        St[k * 64 + t] = p;
        sum += p;
    }
    const float inv = 1.f / sum;
    // PV: o[d] accumulators in registers (reuses q's register budget)
    float o[64];
#pragma unroll
    for (int d = 0; d < 64; d++) o[d] = 0.f;
    for (int k = 0; k < 64; k++) {
        float p = St[k * 64 + t];
#pragma unroll
        for (int d = 0; d < 64; d++) o[d] += p * Vs[k * 64 + d];
    }
    float* orow = g_o + ((size_t)win * 64 + t) * INNERD + hd * 64;
#pragma unroll
    for (int d = 0; d < 64; d++) orow[d] = tf32r(o[d] * inv);
}

extern "C" void kernel_launch(void* const* d_in, const int* in_sizes, int n_in,
                              void* d_out, int out_size) {
    const float* x     = (const float*)d_in[0];
    const float* w_qkv = (const float*)d_in[1];
    const float* w_out = (const float*)d_in[2];
    const float* b_out = (const float*)d_in[3];
    float* out = (float*)d_out;

    perm_wqkv_k<<<1024, 384>>>(w_qkv);
    perm_wout_k<<<512, 1024>>>(w_out, b_out);
    gather_k<<<2048, 256>>>(x);
    gemm_tf32_k<TOKD, QKVD, 0><<<dim3(QKVD / 128, NTOK / 128), 256>>>();
    attn_k<<<dim3(8, 512), 64>>>();
    gemm_tf32_k<INNERD, TOKD, 1><<<dim3(TOKD / 128, NTOK / 128), 256>>>();
    scatter_k<<<2048, 256>>>(out);
}

// round 4
// speedup vs baseline: 1.0504x; 1.0504x over previous
#include <cuda_runtime.h>
#include <cuda_bf16.h>
#include <cstdint>
#include <cstddef>

#define DEV_INLINE __device__ __forceinline__

// B=8, C=64, S=256, WS=32, P=4, HEADS=8, DH=64
constexpr int NTOK = 32768;      // 512 windows * 64 tokens
constexpr int TOKD = 1024;
constexpr int QKVD = 1536;
constexpr int INNERD = 512;

// ---- static scratch ----
__device__ float g_tokens[(size_t)NTOK * TOKD];
__device__ float g_qkv[(size_t)NTOK * QKVD];
__device__ float g_o[(size_t)NTOK * INNERD];
__device__ float g_wqkv[(size_t)TOKD * QKVD];
__device__ float g_wout[(size_t)INNERD * TOKD];
__device__ float g_bias[TOKD];

DEV_INLINE float tf32r(float v) {
    uint32_t u; asm("cvt.rna.tf32.f32 %0, %1;" : "=r"(u) : "f"(v));
    return __uint_as_float(u);
}
DEV_INLINE void mma8(float* d, const uint32_t* a, const uint32_t* b) {
    asm volatile("mma.sync.aligned.m16n8k8.row.col.f32.tf32.tf32.f32 "
        "{%0,%1,%2,%3}, {%4,%5,%6,%7}, {%8,%9}, {%0,%1,%2,%3};"
        : "+f"(d[0]), "+f"(d[1]), "+f"(d[2]), "+f"(d[3])
        : "r"(a[0]), "r"(a[1]), "r"(a[2]), "r"(a[3]), "r"(b[0]), "r"(b[1]));
}
DEV_INLINE void cp16(float* dst, const float* src) {
    uint32_t a = (uint32_t)__cvta_generic_to_shared(dst);
    asm volatile("cp.async.ca.shared.global [%0], [%1], 16;" :: "r"(a), "l"(src));
}

// ---- weight permutation: d' = c*16 + p1*4 + p2 ; orig d = (p1*4+p2)*64 + c ----
__global__ void perm_wqkv_k(const float* __restrict__ w) {
    int dp = blockIdx.x;                       // d' 0..1023
    int src = (dp & 15) * 64 + (dp >> 4);
    float4 v = ((const float4*)(w + (size_t)src * QKVD))[threadIdx.x];  // 384 thr
    v.x = tf32r(v.x); v.y = tf32r(v.y); v.z = tf32r(v.z); v.w = tf32r(v.w);
    ((float4*)(g_wqkv + (size_t)dp * QKVD))[threadIdx.x] = v;
}
__global__ void perm_wout_k(const float* __restrict__ w, const float* __restrict__ b) {
    int e = blockIdx.x;                        // 0..511
    int dp = threadIdx.x;                      // 0..1023
    int src = (dp & 15) * 64 + (dp >> 4);
    g_wout[(size_t)e * TOKD + dp] = tf32r(w[(size_t)e * TOKD + src]);
    if (e == 0) g_bias[dp] = b[src];
}

// ---- gather: x[b,c,h,w] -> tokens[win*64+t][d'] (tf32-rounded) ----
__global__ void gather_k(const float* __restrict__ x) {
    int blk = blockIdx.x;                // 2048 = b*256 + h
    int b = blk >> 8, h = blk & 255;
    int tid = threadIdx.x;               // 256
    int w4 = tid & 63, c0 = tid >> 6;    // w4 = float4 idx over w
    int h1 = h >> 5, hh = h & 31, nh_i = hh >> 2, p1 = hh & 3;
    int w1 = w4 >> 3, nw_j = w4 & 7;
    int win = b * 64 + h1 * 8 + w1;
    int t = nh_i * 8 + nw_j;
    size_t drow = ((size_t)win * 64 + t) * TOKD + p1 * 4;
    size_t sbase = (((size_t)b * 64) * 256 + h) * 256 + w4 * 4;
#pragma unroll
    for (int i = 0; i < 16; i++) {
        int c = c0 * 16 + i;
        float4 v = *(const float4*)&x[sbase + (size_t)c * 65536];
        v.x = tf32r(v.x); v.y = tf32r(v.y); v.z = tf32r(v.z); v.w = tf32r(v.w);
        *(float4*)&g_tokens[drow + (size_t)c * 16] = v;
    }
}

// scatter index for fused out-GEMM epilogue: (row=token, col=d') -> x layout
DEV_INLINE size_t scat_idx(int row, int col) {
    int win = row >> 6, t = row & 63;
    int b = win >> 6, rem = win & 63;       // rem = h1*8 + w1
    int hh = ((rem >> 3) << 5) + ((t >> 3) << 2) + ((col >> 2) & 3);
    int ww = ((rem & 7) << 5) + ((t & 7) << 2) + (col & 3);
    int c = col >> 4;
    return ((((size_t)(b * 64 + c) << 8) + hh) << 8) + ww;
}

// ---- tf32 GEMM: 128x128 tile, K-step 16, double-buffered, 256 thr, 8 warps ----
// MODE 0: g_qkv = g_tokens @ g_wqkv                 (K=1024, N=1536)
// MODE 1: out[scattered] = g_o @ g_wout + bias      (K=512,  N=1024)
template<int K, int N, int MODE>
__global__ void __launch_bounds__(256) gemm_tf32_k(float* __restrict__ outp) {
    __shared__ float As[2][128 * 20];   // [128 rows][16 k], stride 20
    __shared__ float Bs[2][16 * 136];   // [16 k][128 n],  stride 136
    const float* A = (MODE == 0) ? g_tokens : g_o;
    const float* B = (MODE == 0) ? g_wqkv : g_wout;

    const int tid = threadIdx.x, warp = tid >> 5, lane = tid & 31;
    const int wm = warp >> 2, wn = warp & 3;       // 2 x 4 warps
    const int tm = blockIdx.y * 128, tn = blockIdx.x * 128;
    const int r0 = lane >> 2, kk = lane & 3;

    const int ar = tid >> 2, ak4 = tid & 3;        // A loads: row, k-quad
    const int br = tid >> 5, bn4 = tid & 31;       // B loads: k-row, n-quad

    float acc[4][4][4];
#pragma unroll
    for (int mi = 0; mi < 4; mi++)
#pragma unroll
        for (int ni = 0; ni < 4; ni++)
#pragma unroll
            for (int j = 0; j < 4; j++) acc[mi][ni][j] = 0.f;

    constexpr int KT = K / 16;

    // prologue: stage 0
    cp16(&As[0][ar * 20 + ak4 * 4], &A[(size_t)(tm + ar) * K + ak4 * 4]);
    cp16(&As[0][(ar + 64) * 20 + ak4 * 4], &A[(size_t)(tm + ar + 64) * K + ak4 * 4]);
    cp16(&Bs[0][br * 136 + bn4 * 4], &B[(size_t)br * N + tn + bn4 * 4]);
    cp16(&Bs[0][(br + 8) * 136 + bn4 * 4], &B[(size_t)(br + 8) * N + tn + bn4 * 4]);
    asm volatile("cp.async.commit_group;");

    for (int kt = 0; kt < KT; kt++) {
        if (kt + 1 < KT) {
            const int k0 = (kt + 1) * 16, bf = (kt + 1) & 1;
            cp16(&As[bf][ar * 20 + ak4 * 4], &A[(size_t)(tm + ar) * K + k0 + ak4 * 4]);
            cp16(&As[bf][(ar + 64) * 20 + ak4 * 4], &A[(size_t)(tm + ar + 64) * K + k0 + ak4 * 4]);
            cp16(&Bs[bf][br * 136 + bn4 * 4], &B[(size_t)(k0 + br) * N + tn + bn4 * 4]);
            cp16(&Bs[bf][(br + 8) * 136 + bn4 * 4], &B[(size_t)(k0 + br + 8) * N + tn + bn4 * 4]);
            asm volatile("cp.async.commit_group;");
            asm volatile("cp.async.wait_group 1;");
        } else {
            asm volatile("cp.async.wait_group 0;");
        }
        __syncthreads();
        const float* as = As[kt & 1];
        const float* bs = Bs[kt & 1];
#pragma unroll
        for (int k8 = 0; k8 < 2; k8++) {
            const int kb = k8 * 8;
            uint32_t a[4][4], bq[4][2];
#pragma unroll
            for (int mi = 0; mi < 4; mi++) {
                int rb = (wm * 64 + mi * 16) * 20 + kb + kk;
                a[mi][0] = __float_as_uint(as[rb + r0 * 20]);
                a[mi][1] = __float_as_uint(as[rb + (r0 + 8) * 20]);
                a[mi][2] = __float_as_uint(as[rb + r0 * 20 + 4]);
                a[mi][3] = __float_as_uint(as[rb + (r0 + 8) * 20 + 4]);
            }
#pragma unroll
            for (int ni = 0; ni < 4; ni++) {
                int cb = wn * 32 + ni * 8 + r0;
                bq[ni][0] = __float_as_uint(bs[(kb + kk) * 136 + cb]);
                bq[ni][1] = __float_as_uint(bs[(kb + kk + 4) * 136 + cb]);
            }
#pragma unroll
            for (int mi = 0; mi < 4; mi++)
#pragma unroll
                for (int ni = 0; ni < 4; ni++)
                    mma8(acc[mi][ni], a[mi], bq[ni]);
        }
        __syncthreads();
    }
    // epilogue
    const int c2 = (lane & 3) * 2;
#pragma unroll
    for (int mi = 0; mi < 4; mi++) {
#pragma unroll
        for (int ni = 0; ni < 4; ni++) {
            int row = tm + wm * 64 + mi * 16 + r0;
            int col = tn + wn * 32 + ni * 8 + c2;
            if (MODE == 0) {
                *(float2*)&g_qkv[(size_t)row * N + col] =
                    make_float2(acc[mi][ni][0], acc[mi][ni][1]);
                *(float2*)&g_qkv[(size_t)(row + 8) * N + col] =
                    make_float2(acc[mi][ni][2], acc[mi][ni][3]);
            } else {
                float b0 = g_bias[col], b1 = g_bias[col + 1];
                *(float2*)&outp[scat_idx(row, col)] =
                    make_float2(acc[mi][ni][0] + b0, acc[mi][ni][1] + b1);
                *(float2*)&outp[scat_idx(row + 8, col)] =
                    make_float2(acc[mi][ni][2] + b0, acc[mi][ni][3] + b1);
            }
        }
    }
}

// ---- attention: one CTA per (window, head), 64 threads, scores in regs ----
__global__ void __launch_bounds__(64) attn_k() {
    __shared__ float Ks[64 * 64];
    __shared__ float Vs[64 * 64];
    const int win = blockIdx.y, hd = blockIdx.x, t = threadIdx.x;
    const float* base = g_qkv + (size_t)win * 64 * QKVD;
    // cooperative K/V load (coalesced float4)
#pragma unroll
    for (int i = 0; i < 16; i++) {
        int idx = i * 64 + t;
        int r = idx >> 4, v4 = idx & 15;
        *(float4*)&Ks[r * 64 + v4 * 4] =
            *(const float4*)&base[(size_t)r * QKVD + INNERD + hd * 64 + v4 * 4];
        *(float4*)&Vs[r * 64 + v4 * 4] =
            *(const float4*)&base[(size_t)r * QKVD + 2 * INNERD + hd * 64 + v4 * 4];
    }
    float4 q[16];
    const float4* qrow = (const float4*)(base + (size_t)t * QKVD + hd * 64);
#pragma unroll
    for (int i = 0; i < 16; i++) {
        float4 v = qrow[i];
        v.x *= 0.125f; v.y *= 0.125f; v.z *= 0.125f; v.w *= 0.125f;
        q[i] = v;
    }
    __syncthreads();
    // scores for this thread's token (registers), 4-way split accumulators
    float s[64];
#pragma unroll
    for (int k = 0; k < 64; k++) {
        const float4* Kr = (const float4*)&Ks[k * 64];
        float a0 = 0.f, a1 = 0.f, a2 = 0.f, a3 = 0.f;
#pragma unroll
        for (int i = 0; i < 16; i++) {
            float4 kv = Kr[i];
            a0 += q[i].x * kv.x; a1 += q[i].y * kv.y;
            a2 += q[i].z * kv.z; a3 += q[i].w * kv.w;
        }
        s[k] = (a0 + a1) + (a2 + a3);
    }
    float m = -1e30f;
#pragma unroll
    for (int k = 0; k < 64; k++) m = fmaxf(m, s[k]);
    float sum = 0.f;
#pragma unroll
    for (int k = 0; k < 64; k++) { s[k] = __expf(s[k] - m); sum += s[k]; }
    const float inv = 1.f / sum;
    float4 o[16];
#pragma unroll
    for (int i = 0; i < 16; i++) o[i] = make_float4(0.f, 0.f, 0.f, 0.f);
#pragma unroll
    for (int k = 0; k < 64; k++) {
        const float p = s[k];
        const float4* Vr = (const float4*)&Vs[k * 64];
#pragma unroll
        for (int i = 0; i < 16; i++) {
            float4 v = Vr[i];
            o[i].x += p * v.x; o[i].y += p * v.y;
            o[i].z += p * v.z; o[i].w += p * v.w;
        }
    }
    float4* orow = (float4*)(g_o + ((size_t)win * 64 + t) * INNERD + hd * 64);
#pragma unroll
    for (int i = 0; i < 16; i++) {
        float4 v;
        v.x = tf32r(o[i].x * inv); v.y = tf32r(o[i].y * inv);
        v.z = tf32r(o[i].z * inv); v.w = tf32r(o[i].w * inv);
        orow[i] = v;
    }
}

extern "C" void kernel_launch(void* const* d_in, const int* in_sizes, int n_in,
                              void* d_out, int out_size) {
    const float* x     = (const float*)d_in[0];
    const float* w_qkv = (const float*)d_in[1];
    const float* w_out = (const float*)d_in[2];
    const float* b_out = (const float*)d_in[3];
    float* out = (float*)d_out;

    perm_wqkv_k<<<1024, 384>>>(w_qkv);
    perm_wout_k<<<512, 1024>>>(w_out, b_out);
    gather_k<<<2048, 256>>>(x);
    gemm_tf32_k<TOKD, QKVD, 0><<<dim3(QKVD / 128, NTOK / 128), 256>>>(nullptr);
    attn_k<<<dim3(8, 512), 64>>>();
    gemm_tf32_k<INNERD, TOKD, 1><<<dim3(TOKD / 128, NTOK / 128), 256>>>(out);
}